// round 11
// baseline (speedup 1.0000x reference)
#include <cuda_runtime.h>
#include <cuda_bf16.h>
#include <stdint.h>

// RZGate, L=12, D=2, J=1.  S = diag(1,-1) => U is DIAGONAL with
//   theta(row) = -0.5 * sum_i a_i * (bit_i(row) ? -1 : +1)   (site 0 = MSB)
//
// TRUE ABI (validated rounds 9-10): __output__ is FLOAT32 = REAL PART of the
// complex reference (numpy complex64->float32 cast), out_size == NELEMS:
//   out[row,b] = cos(theta(row)) * x[row,b]        (4 MB in, 4 MB out)
// Inputs: x f32[4096*256], angle f32[12], S unused (deterministic).
//
// Round-10 lesson: kernel was latency-bound (occ 38.6%, phase chain computed
// BEFORE loads). This round: 2x warps (one float4 per thread, 1024 blocks)
// and loads issued FIRST so the shfl/cosf phase chain hides under DRAM
// latency. Vector widths still gated per-pointer at runtime (alignment
// never verified).

#define LQ      12
#define NROWS   4096
#define NBATCH  256
#define NELEMS  (NROWS * NBATCH)   // 1,048,576

// ---------------------------------------------------------------------------
// FAST kernel: 1024 blocks x 256 threads, one float4 per thread.
// 64 threads per row -> row is warp-uniform (warps never straddle rows).
// Load x FIRST, then phase via lane-parallel dot + shfl butterfly + one
// cosf per warp, then multiply + store. No smem, no syncthreads.
// ---------------------------------------------------------------------------
__global__ void __launch_bounds__(256)
rz_real(const float* __restrict__ x,
        const float* __restrict__ ang,
        float*       __restrict__ out,
        int xv4, int ov4)
{
    const int tid  = blockIdx.x * blockDim.x + threadIdx.x;
    const int lane = threadIdx.x & 31;
    const int e0   = tid * 4;          // first float of this thread's quad
    const int row  = tid >> 6;         // 64 threads per 256-float row

    // ---- issue the data load FIRST (hides the phase chain) ----
    float v0, v1, v2, v3;
    if (xv4) {
        const float4 a = ((const float4*)x)[tid];
        v0 = a.x; v1 = a.y; v2 = a.z; v3 = a.w;
    } else {
        v0 = __ldg(&x[e0 + 0]);
        v1 = __ldg(&x[e0 + 1]);
        v2 = __ldg(&x[e0 + 2]);
        v3 = __ldg(&x[e0 + 3]);
    }

    // ---- per-row phase (warp-uniform row) ----
    float term = 0.0f;
    if (lane < LQ) {
        const int bit = (row >> (LQ - 1 - lane)) & 1;
        term = ang[lane] * (bit ? -1.0f : 1.0f);
    }
#pragma unroll
    for (int o = 16; o; o >>= 1)
        term += __shfl_xor_sync(0xFFFFFFFFu, term, o);

    float cs = 0.0f;
    if (lane == 0) cs = cosf(-0.5f * term);
    cs = __shfl_sync(0xFFFFFFFFu, cs, 0);

    // ---- multiply + store ----
    if (ov4) {
        ((float4*)out)[tid] = make_float4(cs * v0, cs * v1, cs * v2, cs * v3);
    } else {
        out[e0 + 0] = cs * v0;
        out[e0 + 1] = cs * v1;
        out[e0 + 2] = cs * v2;
        out[e0 + 3] = cs * v3;
    }
}

// ---------------------------------------------------------------------------
// SAFE fallback: all-scalar, dtype-probing, bounds-clamped (proven passing).
// ---------------------------------------------------------------------------
__global__ void __launch_bounds__(256)
rz_safe(const void* __restrict__ xraw, int x_elems,
        const void* __restrict__ araw,
        float* __restrict__ outf, int n_out_floats,
        int interleaved, int x_hint, int a_hint)
{
    __shared__ float2 s_phase[4];
    __shared__ int    s_xbf;
    const int t = threadIdx.x;

    if (t == 0) {
        int xbf = x_hint;
        if (xbf < 0) {
            const unsigned short* h = (const unsigned short*)xraw;
            int match = 0;
            for (int i = 0; i < 32; ++i) {
                const int e = (h[2 * i] >> 7) & 0xFF;
                if (e >= 117 && e <= 132) ++match;
            }
            xbf = (match >= 24) ? 1 : 0;
        }
        s_xbf = xbf;
    }
    __syncthreads();
    const int xbf = s_xbf;

    if (t < 4) {
        const int abf = (a_hint >= 0) ? a_hint : xbf;
        const int row = 4 * blockIdx.x + t;
        float th = 0.0f;
#pragma unroll
        for (int i = 0; i < LQ; ++i) {
            float a;
            if (abf) a = __bfloat162float(((const __nv_bfloat16*)araw)[i]);
            else     a = ((const float*)araw)[i];
            const int bit = (row >> (LQ - 1 - i)) & 1;
            th = fmaf(a, bit ? -1.0f : 1.0f, th);
        }
        th *= -0.5f;
        float sc, cc;
        sincosf(th, &sc, &cc);
        s_phase[t] = make_float2(cc, sc);
    }
    __syncthreads();

    const int    e0 = blockIdx.x * 1024 + 4 * t;
    const float2 p  = s_phase[t >> 6];

    float v[4];
#pragma unroll
    for (int j = 0; j < 4; ++j) {
        const int e = e0 + j;
        v[j] = 0.0f;
        if (e < x_elems) {
            if (xbf) v[j] = __bfloat162float(((const __nv_bfloat16*)xraw)[e]);
            else     v[j] = ((const float*)xraw)[e];
        }
    }
    if (interleaved) {
#pragma unroll
        for (int j = 0; j < 4; ++j) {
            const int idx = 2 * (e0 + j);
            if (idx + 1 < n_out_floats) {
                outf[idx]     = p.x * v[j];
                outf[idx + 1] = p.y * v[j];
            }
        }
    } else {
#pragma unroll
        for (int j = 0; j < 4; ++j)
            if (e0 + j < n_out_floats) outf[e0 + j] = p.x * v[j];
    }
}

extern "C" void kernel_launch(void* const* d_in, const int* in_sizes, int n_in,
                              void* d_out, int out_size)
{
    // Identify inputs: x = largest, angle = sized 12/24/48.
    int ix = -1, ia = -1;
    for (int i = 0; i < n_in; ++i) {
        const int sz = in_sizes[i];
        if (sz == 12 || sz == 24 || sz == 48) ia = i;
        else if (ix < 0 || sz > in_sizes[ix]) ix = i;
    }
    if (ix < 0) return;
    if (ia < 0) ia = (n_in > 1) ? 1 : ix;

    const void* x = d_in[ix];
    const void* a = d_in[ia];

    int a_hint = -1;
    if (in_sizes[ia] == 48) a_hint = 0;
    else if (in_sizes[ia] == 24) a_hint = 1;
    int x_hint = (in_sizes[ix] == 4 * NELEMS) ? 0 : -1;

    int x_elems = in_sizes[ix];
    if (x_elems > NELEMS) x_elems = NELEMS;

    int interleaved, n_out_floats;
    if (out_size >= 2 * NELEMS)  { interleaved = 1; n_out_floats = 2 * NELEMS; }
    else if (out_size >= NELEMS) { interleaved = 0; n_out_floats = NELEMS; }
    else { interleaved = 0; n_out_floats = out_size > 0 ? out_size : 0; }

    const bool fast_ok = !interleaved && n_out_floats == NELEMS &&
                         x_elems == NELEMS && a_hint != 1;

    if (fast_ok) {
        const int xv4 = (((uintptr_t)x     & 15u) == 0);
        const int ov4 = (((uintptr_t)d_out & 15u) == 0);
        rz_real<<<NELEMS / 1024, 256>>>((const float*)x, (const float*)a,
                                        (float*)d_out, xv4, ov4);
    } else {
        rz_safe<<<NELEMS / 1024, 256>>>(x, x_elems, a,
                                        (float*)d_out, n_out_floats,
                                        interleaved, x_hint, a_hint);
    }
}